// round 11
// baseline (speedup 1.0000x reference)
#include <cuda_runtime.h>
#include <cuda_fp16.h>
#include <mma.h>
#include <cstdint>
#include <math.h>

using namespace nvcuda;

#define NTOK 8192
#define HDIM 1024
#define FDIM 4096
#define NEXP 8
#define CAP  1280
#define BUCKET 8192

#define BM 128
#define BN 128
#define BK 32
#define NT_G 128          // 4 warps, each owns a 64x64 tile
#define LDA 40            // BK + 8 halves pad
#define LDB 136           // BN + 8 halves pad
#define NSTG 5
#define A_ST (BM * LDA)   // halves per A stage
#define B_ST (BK * LDB)   // halves per B stage
#define SMEM_NEED (NSTG * (A_ST + B_ST) * 2)   // 94.7KB; >= 64KB epilogue staging

#define SEL_THREADS 1024
#define F2H_BLKS 4096     // w4 / 2048

// ---------------- device scratch (no allocation allowed) ----------------
__device__ __half g_h1[(size_t)NEXP * CAP * FDIM];      // 84 MB fp16
__device__ __half g_xe[(size_t)NEXP * CAP * HDIM];      // 20 MB fp16 gathered A
__device__ __half g_w1h[(size_t)NEXP * HDIM * FDIM];    // 64 MB fp16 [E][K][N]
__device__ __half g_w2h[(size_t)NEXP * FDIM * HDIM];    // 64 MB fp16 [E][K][N]
__device__ float  g_accum[(size_t)NTOK * HDIM];         // 32 MB
__device__ unsigned long long g_bucket[NEXP * BUCKET];
__device__ int    g_cnt[NEXP];
__device__ int    g_tok[NEXP * CAP];
__device__ float  g_gate[NEXP * CAP];
__device__ int    g_kept[NEXP];

// ---------------- helpers ----------------
__device__ __forceinline__ uint32_t smem_u32(const void* p) {
    uint32_t a;
    asm("{ .reg .u64 t; cvta.to.shared.u64 t, %1; cvt.u32.u64 %0, t; }" : "=r"(a) : "l"(p));
    return a;
}
__device__ __forceinline__ void cp16(uint32_t s, const void* g) {
    asm volatile("cp.async.cg.shared.global [%0], [%1], 16;" :: "r"(s), "l"(g));
}
#define CP_COMMIT() asm volatile("cp.async.commit_group;" ::: "memory")
template <int N>
__device__ __forceinline__ void cp_wait() {
    asm volatile("cp.async.wait_group %0;" :: "n"(N) : "memory");
}

// ---------------- init: accum = hidden (residual), zero counts for next call ----------------
__global__ void init_kernel(const float* __restrict__ hidden) {
    size_t i = (size_t)blockIdx.x * blockDim.x + threadIdx.x;
    const float4* src = (const float4*)hidden;
    float4* dst = (float4*)g_accum;
    size_t n4 = (size_t)NTOK * HDIM / 4;
    if (i < n4) dst[i] = src[i];
    if (blockIdx.x == 0 && threadIdx.x < NEXP) g_cnt[threadIdx.x] = 0;
}

// ---------------- fused: f2h(W1) + f2h(W2) + router, block-partitioned ----------------
__device__ __forceinline__ void f2h_body(const float* __restrict__ s, __half* __restrict__ d,
                                         int blk) {
    size_t n4 = (size_t)NEXP * HDIM * FDIM / 4;
    size_t base = (size_t)blk * blockDim.x * 4 + threadIdx.x;
    float4 v[4];
    size_t idx[4];
#pragma unroll
    for (int i = 0; i < 4; i++) {
        idx[i] = base + (size_t)i * blockDim.x;
        if (idx[i] < n4) v[i] = ((const float4*)s)[idx[i]];
    }
#pragma unroll
    for (int i = 0; i < 4; i++) {
        if (idx[i] < n4) {
            __half2* dd = (__half2*)d;
            dd[2 * idx[i] + 0] = __floats2half2_rn(v[i].x, v[i].y);
            dd[2 * idx[i] + 1] = __floats2half2_rn(v[i].z, v[i].w);
        }
    }
}

__global__ __launch_bounds__(512) void fused_pre(const float* __restrict__ hidden,
                                                 const float* __restrict__ Wr,
                                                 const float* __restrict__ br,
                                                 const float* __restrict__ W1,
                                                 const float* __restrict__ W2,
                                                 __half* __restrict__ w1h,
                                                 __half* __restrict__ w2h) {
    int b = blockIdx.x;
    if (b < F2H_BLKS) { f2h_body(W1, w1h, b); return; }
    if (b < 2 * F2H_BLKS) { f2h_body(W2, w2h, b - F2H_BLKS); return; }

    // router: 64 tokens per block, 512 threads (16 warps x 4 tokens)
    __shared__ float sWt[NEXP * HDIM];   // [e][k], 32KB
    int tid = threadIdx.x;
    for (int k = tid; k < HDIM; k += 512) {
        float4 a = ((const float4*)(Wr + k * NEXP))[0];
        float4 bb = ((const float4*)(Wr + k * NEXP))[1];
        sWt[0 * HDIM + k] = a.x; sWt[1 * HDIM + k] = a.y;
        sWt[2 * HDIM + k] = a.z; sWt[3 * HDIM + k] = a.w;
        sWt[4 * HDIM + k] = bb.x; sWt[5 * HDIM + k] = bb.y;
        sWt[6 * HDIM + k] = bb.z; sWt[7 * HDIM + k] = bb.w;
    }
    __syncthreads();

    int rb = b - 2 * F2H_BLKS;
    int warp = tid >> 5, lane = tid & 31;
#pragma unroll
    for (int t = 0; t < 4; t++) {
        int tok = rb * 64 + warp * 4 + t;
        const float4* xr = (const float4*)(hidden + (size_t)tok * HDIM);
        float acc[NEXP];
#pragma unroll
        for (int e = 0; e < NEXP; e++) acc[e] = 0.f;
#pragma unroll
        for (int i = 0; i < 8; i++) {
            float4 v = xr[lane + 32 * i];
#pragma unroll
            for (int e = 0; e < NEXP; e++) {
                float4 w = ((const float4*)(sWt + e * HDIM))[lane + 32 * i];
                acc[e] += v.x * w.x + v.y * w.y + v.z * w.z + v.w * w.w;
            }
        }
#pragma unroll
        for (int o = 16; o; o >>= 1)
#pragma unroll
            for (int e = 0; e < NEXP; e++) acc[e] += __shfl_xor_sync(0xFFFFFFFFu, acc[e], o);
        if (lane == 0) {
#pragma unroll
            for (int e = 0; e < NEXP; e++) acc[e] += br[e];
            int i0 = 0;
#pragma unroll
            for (int e = 1; e < NEXP; e++) if (acc[e] > acc[i0]) i0 = e;
            int i1 = -1;
#pragma unroll
            for (int e = 0; e < NEXP; e++) {
                if (e == i0) continue;
                if (i1 < 0 || acc[e] > acc[i1]) i1 = e;
            }
            float v0 = acc[i0], v1 = acc[i1];
            float e1 = __expf(v1 - v0);
            float inv = 1.f / (1.f + e1);
            float w0 = inv, w1 = e1 * inv;
            unsigned f0 = (unsigned)(tok * 2 + 0);
            unsigned f1 = (unsigned)(tok * 2 + 1);
            int p0 = atomicAdd(&g_cnt[i0], 1);
            g_bucket[i0 * BUCKET + p0] =
                ((unsigned long long)__float_as_uint(w0) << 32) | (0xFFFFFFFFu - f0);
            int p1 = atomicAdd(&g_cnt[i1], 1);
            g_bucket[i1 * BUCKET + p1] =
                ((unsigned long long)__float_as_uint(w1) << 32) | (0xFFFFFFFFu - f1);
        }
    }
}

// ---------------- per-expert capacity selection: radix select (order-free) ----------------
__global__ void select_kernel() {
    extern __shared__ unsigned long long skeys[];   // up to BUCKET keys (64KB)
    __shared__ int hist[256];
    __shared__ unsigned long long s_thr;
    __shared__ int s_rem;
    __shared__ int pos;
    int e = blockIdx.x;
    int cnt = g_cnt[e];
    int tid = threadIdx.x;
    for (int i = tid; i < cnt; i += SEL_THREADS)
        skeys[i] = g_bucket[e * BUCKET + i];
    int kept = min(cnt, CAP);
    if (tid == 0) { g_kept[e] = kept; pos = 0; }
    __syncthreads();

    unsigned long long thr = 0ULL;
    if (cnt > CAP) {
        unsigned long long prefix = 0ULL;
        int remaining = kept;
        for (int level = 7; level >= 0; level--) {
            for (int i = tid; i < 256; i += SEL_THREADS) hist[i] = 0;
            __syncthreads();
            int sh = level * 8;
            unsigned long long pmask = (level == 7) ? 0ULL : (~0ULL << (sh + 8));
            for (int i = tid; i < cnt; i += SEL_THREADS) {
                unsigned long long k = skeys[i];
                if ((k & pmask) == prefix)
                    atomicAdd(&hist[(int)((k >> sh) & 0xFF)], 1);
            }
            __syncthreads();
            if (tid == 0) {
                int cum = 0, b = 255;
                for (; b > 0; b--) {
                    if (cum + hist[b] >= remaining) break;
                    cum += hist[b];
                }
                s_rem = remaining - cum;
                s_thr = prefix | ((unsigned long long)b << sh);
            }
            __syncthreads();
            prefix = s_thr;
            remaining = s_rem;
            __syncthreads();
        }
        thr = prefix;   // exactly kept keys satisfy key >= thr
    }

    for (int i = tid; i < cnt; i += SEL_THREADS) {
        unsigned long long k = skeys[i];
        if (k >= thr) {
            int p = atomicAdd(&pos, 1);
            unsigned flat = 0xFFFFFFFFu - (unsigned)(k & 0xFFFFFFFFu);
            g_tok[e * CAP + p] = (int)(flat >> 1);
            g_gate[e * CAP + p] = __uint_as_float((unsigned)(k >> 32));
        }
    }
    __syncthreads();
    for (int i = kept + tid; i < CAP; i += SEL_THREADS) {
        g_tok[e * CAP + i] = -1;
        g_gate[e * CAP + i] = 0.f;
    }
}

// ---------------- gather: pack x[tok] -> fp16 dense A; zero padding ----------------
__global__ void gather_kernel(const float* __restrict__ x) {
    int slot = blockIdx.x;
    int tok = g_tok[slot];
    __half2* dst = (__half2*)(g_xe + (size_t)slot * HDIM);
    int t = threadIdx.x;
    if (tok >= 0) {
        float4 v = ((const float4*)(x + (size_t)tok * HDIM))[t];
        dst[2 * t + 0] = __floats2half2_rn(v.x, v.y);
        dst[2 * t + 1] = __floats2half2_rn(v.z, v.w);
    } else {
        dst[2 * t + 0] = __half2half2(__float2half(0.f));
        dst[2 * t + 1] = __half2half2(__float2half(0.f));
    }
}

// ---------------- stage loader: A [BM x BK], B [BK x BN] fp16, 128 threads ----------------
__device__ __forceinline__ void load_stage(int tid, uint32_t sAb, uint32_t sBb, int s,
                                           const __half* Ab, const __half* Bb,
                                           int astr, int bstr, int kt) {
#pragma unroll
    for (int i = 0; i < 4; i++) {          // A: 128 rows x 4 chunks(16B) = 512
        int c = tid + NT_G * i;
        int r = c >> 2, ch = c & 3;
        cp16(sAb + ((uint32_t)(s * A_ST + r * LDA + ch * 8)) * 2,
             Ab + (size_t)r * astr + kt * BK + ch * 8);
    }
#pragma unroll
    for (int i = 0; i < 4; i++) {          // B: 32 rows x 16 chunks(16B) = 512
        int c = tid + NT_G * i;
        int r = c >> 4, ch = c & 15;
        cp16(sBb + ((uint32_t)(s * B_ST + r * LDB + ch * 8)) * 2,
             Bb + (size_t)(kt * BK + r) * bstr + ch * 8);
    }
}

// ---------------- fp16 wmma GEMM, 4 warps x (64x64), vectorized epilogue ----------------
// G1:  h1 = gelu(x[tok] @ W1 + b1)
// !G1: accum[tok] += gate*(h1 @ W2 + b2)
template <int KT, int AST, int BST, bool G1>
__global__ void __launch_bounds__(NT_G) gemm_h(const float* __restrict__ bias) {
    int e = blockIdx.z;
    int kept = g_kept[e];
    int m0 = blockIdx.y * BM;
    if (m0 >= kept) return;
    int n0 = blockIdx.x * BN;

    extern __shared__ __half smem[];
    __half* sA = smem;
    __half* sB = smem + NSTG * A_ST;
    uint32_t sAb = smem_u32(sA), sBb = smem_u32(sB);

    int tid = threadIdx.x;
    int warpId = tid >> 5, lane = tid & 31;
    int wm = warpId & 1, wn = warpId >> 1;    // 2x2 warp grid, 64x64 each

    const __half* Ab;
    const __half* Bb;
    if (G1) {
        Ab = g_xe + (size_t)(e * CAP + m0) * AST;
        Bb = g_w1h + (size_t)e * HDIM * FDIM + n0;
    } else {
        Ab = g_h1 + (size_t)(e * CAP + m0) * AST;
        Bb = g_w2h + (size_t)e * FDIM * HDIM + n0;
    }

    wmma::fragment<wmma::accumulator, 16, 16, 16, float> acc[4][4];
#pragma unroll
    for (int i = 0; i < 4; i++)
#pragma unroll
        for (int j = 0; j < 4; j++) wmma::fill_fragment(acc[i][j], 0.f);

#pragma unroll
    for (int s = 0; s < NSTG - 1; s++) {
        load_stage(tid, sAb, sBb, s, Ab, Bb, AST, BST, s);
        CP_COMMIT();
    }

    for (int kt = 0; kt < KT; kt++) {
        cp_wait<NSTG - 2>();
        __syncthreads();
        if (kt + NSTG - 1 < KT)
            load_stage(tid, sAb, sBb, (kt + NSTG - 1) % NSTG, Ab, Bb, AST, BST, kt + NSTG - 1);
        CP_COMMIT();

        int st = kt % NSTG;
#pragma unroll
        for (int ks = 0; ks < BK; ks += 16) {
            wmma::fragment<wmma::matrix_a, 16, 16, 16, __half, wmma::row_major> af[4];
#pragma unroll
            for (int i = 0; i < 4; i++)
                wmma::load_matrix_sync(af[i], &sA[st * A_ST + (wm * 64 + i * 16) * LDA + ks], LDA);
            wmma::fragment<wmma::matrix_b, 16, 16, 16, __half, wmma::row_major> bf[4];
#pragma unroll
            for (int j = 0; j < 4; j++)
                wmma::load_matrix_sync(bf[j], &sB[st * B_ST + ks * LDB + wn * 64 + j * 16], LDB);
#pragma unroll
            for (int i = 0; i < 4; i++)
#pragma unroll
                for (int j = 0; j < 4; j++)
                    wmma::mma_sync(acc[i][j], af[i], bf[j], acc[i][j]);
        }
        __syncthreads();
    }

    // drain pipeline fully, then reuse stage smem: 64x64 fp32 tile per warp
    cp_wait<0>();
    __syncthreads();
    float* wtile = (float*)smem + warpId * 64 * 64;   // 16KB per warp, 64KB total
#pragma unroll
    for (int i = 0; i < 4; i++)
#pragma unroll
        for (int j = 0; j < 4; j++)
            wmma::store_matrix_sync(&wtile[(i * 16) * 64 + j * 16], acc[i][j], 64,
                                    wmma::mem_row_major);
    __syncwarp();

    int gm0 = m0 + wm * 64;           // global row base for this warp
    int gn0 = n0 + wn * 64;           // global col base

    if (G1) {
        const float* brow = bias + (size_t)e * FDIM + gn0;
#pragma unroll
        for (int it = 0; it < 16; it++) {
            int chunk = lane + 32 * it;
            int r = chunk >> 3, c8 = (chunk & 7) * 8;
            int m = gm0 + r;
            if (m < kept) {
                float4 v0 = *(float4*)&wtile[r * 64 + c8];
                float4 v1 = *(float4*)&wtile[r * 64 + c8 + 4];
                float4 b0 = *(const float4*)&brow[c8];
                float4 b1 = *(const float4*)&brow[c8 + 4];
                float x0 = v0.x + b0.x, x1 = v0.y + b0.y, x2 = v0.z + b0.z, x3 = v0.w + b0.w;
                float x4 = v1.x + b1.x, x5 = v1.y + b1.y, x6 = v1.z + b1.z, x7 = v1.w + b1.w;
                const float IS2 = 0.70710678118654752f;
                x0 = 0.5f * x0 * (1.f + erff(x0 * IS2));
                x1 = 0.5f * x1 * (1.f + erff(x1 * IS2));
                x2 = 0.5f * x2 * (1.f + erff(x2 * IS2));
                x3 = 0.5f * x3 * (1.f + erff(x3 * IS2));
                x4 = 0.5f * x4 * (1.f + erff(x4 * IS2));
                x5 = 0.5f * x5 * (1.f + erff(x5 * IS2));
                x6 = 0.5f * x6 * (1.f + erff(x6 * IS2));
                x7 = 0.5f * x7 * (1.f + erff(x7 * IS2));
                __half2 h0 = __floats2half2_rn(x0, x1);
                __half2 h1 = __floats2half2_rn(x2, x3);
                __half2 h2 = __floats2half2_rn(x4, x5);
                __half2 h3 = __floats2half2_rn(x6, x7);
                uint4 pkt;
                pkt.x = *(uint32_t*)&h0; pkt.y = *(uint32_t*)&h1;
                pkt.z = *(uint32_t*)&h2; pkt.w = *(uint32_t*)&h3;
                *(uint4*)(g_h1 + ((size_t)e * CAP + m) * FDIM + gn0 + c8) = pkt;
            }
        }
    } else {
        const float* brow = bias + (size_t)e * HDIM + gn0;
#pragma unroll
        for (int it = 0; it < 16; it++) {
            int chunk = lane + 32 * it;
            int r = chunk >> 3, c8 = (chunk & 7) * 8;
            int m = gm0 + r;
            int tok = (m < kept) ? g_tok[e * CAP + m] : -1;
            if (tok >= 0) {
                float gate = g_gate[e * CAP + m];
                float4 v0 = *(float4*)&wtile[r * 64 + c8];
                float4 v1 = *(float4*)&wtile[r * 64 + c8 + 4];
                float4 b0 = *(const float4*)&brow[c8];
                float4 b1 = *(const float4*)&brow[c8 + 4];
                float* arow = g_accum + (size_t)tok * HDIM + gn0 + c8;
                atomicAdd(&arow[0], (v0.x + b0.x) * gate);
                atomicAdd(&arow[1], (v0.y + b0.y) * gate);
                atomicAdd(&arow[2], (v0.z + b0.z) * gate);
                atomicAdd(&arow[3], (v0.w + b0.w) * gate);
                atomicAdd(&arow[4], (v1.x + b1.x) * gate);
                atomicAdd(&arow[5], (v1.y + b1.y) * gate);
                atomicAdd(&arow[6], (v1.z + b1.z) * gate);
                atomicAdd(&arow[7], (v1.w + b1.w) * gate);
            }
        }
    }
}

// ---------------- LayerNorm over accum -> out ----------------
__global__ void ln_kernel(const float* __restrict__ gamma,
                          const float* __restrict__ beta,
                          float* __restrict__ out) {
    int row = blockIdx.x, tid = threadIdx.x;
    const float4* a = (const float4*)(g_accum + (size_t)row * HDIM);
    float4 v = a[tid];
    float s = v.x + v.y + v.z + v.w;
    float q = v.x * v.x + v.y * v.y + v.z * v.z + v.w * v.w;
#pragma unroll
    for (int o = 16; o; o >>= 1) {
        s += __shfl_xor_sync(0xFFFFFFFFu, s, o);
        q += __shfl_xor_sync(0xFFFFFFFFu, q, o);
    }
    __shared__ float ss[8], sq[8];
    if ((tid & 31) == 0) { ss[tid >> 5] = s; sq[tid >> 5] = q; }
    __syncthreads();
    if (tid < 32) {
        s = (tid < 8) ? ss[tid] : 0.f;
        q = (tid < 8) ? sq[tid] : 0.f;
#pragma unroll
        for (int o = 4; o; o >>= 1) {
            s += __shfl_xor_sync(0xFFFFFFFFu, s, o);
            q += __shfl_xor_sync(0xFFFFFFFFu, q, o);
        }
        if (tid == 0) { ss[0] = s; sq[0] = q; }
    }
    __syncthreads();
    float mu = ss[0] * (1.f / HDIM);
    float var = sq[0] * (1.f / HDIM) - mu * mu;
    float rs = rsqrtf(var + 1e-5f);
    float4 gv = ((const float4*)gamma)[tid];
    float4 bv = ((const float4*)beta)[tid];
    float4 o4;
    o4.x = (v.x - mu) * rs * gv.x + bv.x;
    o4.y = (v.y - mu) * rs * gv.y + bv.y;
    o4.z = (v.z - mu) * rs * gv.z + bv.z;
    o4.w = (v.w - mu) * rs * gv.w + bv.w;
    ((float4*)(out + (size_t)row * HDIM))[tid] = o4;
}

// ---------------- launch (single stream; gemm1 is the 4th launch -> ncu samples it) ----------------
extern "C" void kernel_launch(void* const* d_in, const int* in_sizes, int n_in,
                              void* d_out, int out_size) {
    const float* hidden = (const float*)d_in[0];
    const float* Wr     = (const float*)d_in[1];
    const float* br     = (const float*)d_in[2];
    const float* W1     = (const float*)d_in[3];
    const float* b1     = (const float*)d_in[4];
    const float* W2     = (const float*)d_in[5];
    const float* b2     = (const float*)d_in[6];
    const float* gamma  = (const float*)d_in[7];
    const float* beta   = (const float*)d_in[8];
    float* out = (float*)d_out;

    cudaFuncSetAttribute(select_kernel, cudaFuncAttributeMaxDynamicSharedMemorySize,
                         BUCKET * sizeof(unsigned long long));
    cudaFuncSetAttribute(gemm_h<HDIM / BK, HDIM, FDIM, true>,
                         cudaFuncAttributeMaxDynamicSharedMemorySize, SMEM_NEED);
    cudaFuncSetAttribute(gemm_h<FDIM / BK, FDIM, HDIM, false>,
                         cudaFuncAttributeMaxDynamicSharedMemorySize, SMEM_NEED);

    __half* w1h; cudaGetSymbolAddress((void**)&w1h, g_w1h);
    __half* w2h; cudaGetSymbolAddress((void**)&w2h, g_w2h);

    size_t n4 = (size_t)NTOK * HDIM / 4;

    fused_pre<<<2 * F2H_BLKS + NTOK / 64, 512>>>(hidden, Wr, br, W1, W2, w1h, w2h); // 1
    select_kernel<<<NEXP, SEL_THREADS, BUCKET * sizeof(unsigned long long)>>>();    // 2
    gather_kernel<<<NEXP * CAP, 256>>>(hidden);                                     // 3
    gemm_h<HDIM / BK, HDIM, FDIM, true>                                             // 4 <- ncu
        <<<dim3(FDIM / BN, CAP / BM, NEXP), NT_G, SMEM_NEED>>>(b1);
    init_kernel<<<(unsigned)((n4 + 511) / 512), 512>>>(hidden);                     // 5
    gemm_h<FDIM / BK, FDIM, HDIM, false>                                            // 6
        <<<dim3(HDIM / BN, CAP / BM, NEXP), NT_G, SMEM_NEED>>>(b2);
    ln_kernel<<<NTOK, 256>>>(gamma, beta, out);                                     // 7
}

// round 12
// speedup vs baseline: 1.2380x; 1.2380x over previous
#include <cuda_runtime.h>
#include <cuda_fp16.h>
#include <mma.h>
#include <cstdint>
#include <math.h>

using namespace nvcuda;

#define NTOK 8192
#define HDIM 1024
#define FDIM 4096
#define NEXP 8
#define CAP  1280
#define BUCKET 8192

#define BM 128
#define BN 128
#define BK 32
#define NT_G 128          // 4 warps, each owns a 64x64 tile
#define LDA 40            // BK + 8 halves pad
#define LDB 136           // BN + 8 halves pad
#define NSTG 3
#define A_ST (BM * LDA)   // halves per A stage
#define B_ST (BK * LDB)   // halves per B stage
#define SMEM_NEED (NSTG * (A_ST + B_ST) * 2)   // 56,832 B -> 3 CTAs/SM

#define SEL_THREADS 1024

// ---------------- device scratch (no allocation allowed) ----------------
__device__ __half g_h1[(size_t)NEXP * CAP * FDIM];      // 84 MB fp16
__device__ __half g_xe[(size_t)NEXP * CAP * HDIM];      // 20 MB fp16 gathered A
__device__ __half g_w1h[(size_t)NEXP * HDIM * FDIM];    // 64 MB fp16 [E][K][N]
__device__ __half g_w2h[(size_t)NEXP * FDIM * HDIM];    // 64 MB fp16 [E][K][N]
__device__ float  g_accum[(size_t)NTOK * HDIM];         // 32 MB
__device__ unsigned long long g_bucket[NEXP * BUCKET];
__device__ int    g_cnt[NEXP];
__device__ int    g_tok[NEXP * CAP];
__device__ float  g_gate[NEXP * CAP];
__device__ int    g_kept[NEXP];

// ---------------- helpers ----------------
__device__ __forceinline__ uint32_t smem_u32(const void* p) {
    uint32_t a;
    asm("{ .reg .u64 t; cvta.to.shared.u64 t, %1; cvt.u32.u64 %0, t; }" : "=r"(a) : "l"(p));
    return a;
}
__device__ __forceinline__ void cp16(uint32_t s, const void* g) {
    asm volatile("cp.async.cg.shared.global [%0], [%1], 16;" :: "r"(s), "l"(g));
}
#define CP_COMMIT() asm volatile("cp.async.commit_group;" ::: "memory")
template <int N>
__device__ __forceinline__ void cp_wait() {
    asm volatile("cp.async.wait_group %0;" :: "n"(N) : "memory");
}

// ---------------- init: accum = hidden (residual), zero counts for next call ----------------
__global__ void init_kernel(const float* __restrict__ hidden) {
    size_t i = (size_t)blockIdx.x * blockDim.x + threadIdx.x;
    const float4* src = (const float4*)hidden;
    float4* dst = (float4*)g_accum;
    size_t n4 = (size_t)NTOK * HDIM / 4;
    if (i < n4) dst[i] = src[i];
    if (blockIdx.x == 0 && threadIdx.x < NEXP) g_cnt[threadIdx.x] = 0;
}

// ---------------- fp32 -> fp16 conversion (4x float4 per thread for MLP) ----------------
__global__ void f2h_kernel(const float* __restrict__ s, __half* __restrict__ d, size_t n4) {
    size_t base = (size_t)blockIdx.x * blockDim.x * 4 + threadIdx.x;
    float4 v[4];
    size_t idx[4];
#pragma unroll
    for (int i = 0; i < 4; i++) {
        idx[i] = base + (size_t)i * blockDim.x;
        if (idx[i] < n4) v[i] = ((const float4*)s)[idx[i]];
    }
#pragma unroll
    for (int i = 0; i < 4; i++) {
        if (idx[i] < n4) {
            __half2* dd = (__half2*)d;
            dd[2 * idx[i] + 0] = __floats2half2_rn(v[i].x, v[i].y);
            dd[2 * idx[i] + 1] = __floats2half2_rn(v[i].z, v[i].w);
        }
    }
}

// ---------------- router: 32 tokens/block, Wr transposed in smem ----------------
__global__ __launch_bounds__(256) void router_kernel(const float* __restrict__ x,
                                                     const float* __restrict__ Wr,
                                                     const float* __restrict__ br) {
    __shared__ float sWt[NEXP * HDIM];   // [e][k], 32KB
    int tid = threadIdx.x;
    for (int k = tid; k < HDIM; k += 256) {
        float4 a = ((const float4*)(Wr + k * NEXP))[0];
        float4 b = ((const float4*)(Wr + k * NEXP))[1];
        sWt[0 * HDIM + k] = a.x; sWt[1 * HDIM + k] = a.y;
        sWt[2 * HDIM + k] = a.z; sWt[3 * HDIM + k] = a.w;
        sWt[4 * HDIM + k] = b.x; sWt[5 * HDIM + k] = b.y;
        sWt[6 * HDIM + k] = b.z; sWt[7 * HDIM + k] = b.w;
    }
    __syncthreads();

    int warp = tid >> 5, lane = tid & 31;
#pragma unroll
    for (int t = 0; t < 4; t++) {
        int tok = blockIdx.x * 32 + warp * 4 + t;
        const float4* xr = (const float4*)(x + (size_t)tok * HDIM);
        float acc[NEXP];
#pragma unroll
        for (int e = 0; e < NEXP; e++) acc[e] = 0.f;
#pragma unroll
        for (int i = 0; i < 8; i++) {
            float4 v = xr[lane + 32 * i];
#pragma unroll
            for (int e = 0; e < NEXP; e++) {
                float4 w = ((const float4*)(sWt + e * HDIM))[lane + 32 * i];
                acc[e] += v.x * w.x + v.y * w.y + v.z * w.z + v.w * w.w;
            }
        }
#pragma unroll
        for (int o = 16; o; o >>= 1)
#pragma unroll
            for (int e = 0; e < NEXP; e++) acc[e] += __shfl_xor_sync(0xFFFFFFFFu, acc[e], o);
        if (lane == 0) {
#pragma unroll
            for (int e = 0; e < NEXP; e++) acc[e] += br[e];
            int i0 = 0;
#pragma unroll
            for (int e = 1; e < NEXP; e++) if (acc[e] > acc[i0]) i0 = e;
            int i1 = -1;
#pragma unroll
            for (int e = 0; e < NEXP; e++) {
                if (e == i0) continue;
                if (i1 < 0 || acc[e] > acc[i1]) i1 = e;
            }
            float v0 = acc[i0], v1 = acc[i1];
            float e1 = __expf(v1 - v0);
            float inv = 1.f / (1.f + e1);
            float w0 = inv, w1 = e1 * inv;
            unsigned f0 = (unsigned)(tok * 2 + 0);
            unsigned f1 = (unsigned)(tok * 2 + 1);
            int p0 = atomicAdd(&g_cnt[i0], 1);
            g_bucket[i0 * BUCKET + p0] =
                ((unsigned long long)__float_as_uint(w0) << 32) | (0xFFFFFFFFu - f0);
            int p1 = atomicAdd(&g_cnt[i1], 1);
            g_bucket[i1 * BUCKET + p1] =
                ((unsigned long long)__float_as_uint(w1) << 32) | (0xFFFFFFFFu - f1);
        }
    }
}

// ---------------- per-expert capacity selection: radix select (order-free) ----------------
__global__ void select_kernel() {
    extern __shared__ unsigned long long skeys[];   // up to BUCKET keys (64KB)
    __shared__ int hist[256];
    __shared__ unsigned long long s_thr;
    __shared__ int s_rem;
    __shared__ int pos;
    int e = blockIdx.x;
    int cnt = g_cnt[e];
    int tid = threadIdx.x;
    for (int i = tid; i < cnt; i += SEL_THREADS)
        skeys[i] = g_bucket[e * BUCKET + i];
    int kept = min(cnt, CAP);
    if (tid == 0) { g_kept[e] = kept; pos = 0; }
    __syncthreads();

    unsigned long long thr = 0ULL;
    if (cnt > CAP) {
        unsigned long long prefix = 0ULL;
        int remaining = kept;
        for (int level = 7; level >= 0; level--) {
            for (int i = tid; i < 256; i += SEL_THREADS) hist[i] = 0;
            __syncthreads();
            int sh = level * 8;
            unsigned long long pmask = (level == 7) ? 0ULL : (~0ULL << (sh + 8));
            for (int i = tid; i < cnt; i += SEL_THREADS) {
                unsigned long long k = skeys[i];
                if ((k & pmask) == prefix)
                    atomicAdd(&hist[(int)((k >> sh) & 0xFF)], 1);
            }
            __syncthreads();
            if (tid == 0) {
                int cum = 0, b = 255;
                for (; b > 0; b--) {
                    if (cum + hist[b] >= remaining) break;
                    cum += hist[b];
                }
                s_rem = remaining - cum;
                s_thr = prefix | ((unsigned long long)b << sh);
            }
            __syncthreads();
            prefix = s_thr;
            remaining = s_rem;
            __syncthreads();
        }
        thr = prefix;   // exactly kept keys satisfy key >= thr
    }

    for (int i = tid; i < cnt; i += SEL_THREADS) {
        unsigned long long k = skeys[i];
        if (k >= thr) {
            int p = atomicAdd(&pos, 1);
            unsigned flat = 0xFFFFFFFFu - (unsigned)(k & 0xFFFFFFFFu);
            g_tok[e * CAP + p] = (int)(flat >> 1);
            g_gate[e * CAP + p] = __uint_as_float((unsigned)(k >> 32));
        }
    }
    __syncthreads();
    for (int i = kept + tid; i < CAP; i += SEL_THREADS) {
        g_tok[e * CAP + i] = -1;
        g_gate[e * CAP + i] = 0.f;
    }
}

// ---------------- gather: pack x[tok] -> fp16 dense A; zero padding ----------------
__global__ void gather_kernel(const float* __restrict__ x) {
    int slot = blockIdx.x;
    int tok = g_tok[slot];
    __half2* dst = (__half2*)(g_xe + (size_t)slot * HDIM);
    int t = threadIdx.x;
    if (tok >= 0) {
        float4 v = ((const float4*)(x + (size_t)tok * HDIM))[t];
        dst[2 * t + 0] = __floats2half2_rn(v.x, v.y);
        dst[2 * t + 1] = __floats2half2_rn(v.z, v.w);
    } else {
        dst[2 * t + 0] = __half2half2(__float2half(0.f));
        dst[2 * t + 1] = __half2half2(__float2half(0.f));
    }
}

// ---------------- stage loader: A [BM x BK], B [BK x BN] fp16, 128 threads ----------------
__device__ __forceinline__ void load_stage(int tid, uint32_t sAb, uint32_t sBb, int s,
                                           const __half* Ab, const __half* Bb,
                                           int astr, int bstr, int kt) {
#pragma unroll
    for (int i = 0; i < 4; i++) {          // A: 128 rows x 4 chunks(16B) = 512
        int c = tid + NT_G * i;
        int r = c >> 2, ch = c & 3;
        cp16(sAb + ((uint32_t)(s * A_ST + r * LDA + ch * 8)) * 2,
             Ab + (size_t)r * astr + kt * BK + ch * 8);
    }
#pragma unroll
    for (int i = 0; i < 4; i++) {          // B: 32 rows x 16 chunks(16B) = 512
        int c = tid + NT_G * i;
        int r = c >> 4, ch = c & 15;
        cp16(sBb + ((uint32_t)(s * B_ST + r * LDB + ch * 8)) * 2,
             Bb + (size_t)(kt * BK + r) * bstr + ch * 8);
    }
}

// ---------------- fp16 wmma GEMM, 4 warps x (64x64), 3 CTAs/SM ----------------
// G1:  h1 = gelu(x[tok] @ W1 + b1)
// !G1: accum[tok] += gate*(h1 @ W2 + b2)
template <int KT, int AST, int BST, bool G1>
__global__ void __launch_bounds__(NT_G, 3) gemm_h(const float* __restrict__ bias) {
    int e = blockIdx.z;
    int kept = g_kept[e];
    int m0 = blockIdx.y * BM;
    if (m0 >= kept) return;
    int n0 = blockIdx.x * BN;

    extern __shared__ __half smem[];
    __half* sA = smem;
    __half* sB = smem + NSTG * A_ST;
    uint32_t sAb = smem_u32(sA), sBb = smem_u32(sB);

    int tid = threadIdx.x;
    int warpId = tid >> 5, lane = tid & 31;
    int wm = warpId & 1, wn = warpId >> 1;    // 2x2 warp grid, 64x64 each

    const __half* Ab;
    const __half* Bb;
    if (G1) {
        Ab = g_xe + (size_t)(e * CAP + m0) * AST;
        Bb = g_w1h + (size_t)e * HDIM * FDIM + n0;
    } else {
        Ab = g_h1 + (size_t)(e * CAP + m0) * AST;
        Bb = g_w2h + (size_t)e * FDIM * HDIM + n0;
    }

    wmma::fragment<wmma::accumulator, 16, 16, 16, float> acc[4][4];
#pragma unroll
    for (int i = 0; i < 4; i++)
#pragma unroll
        for (int j = 0; j < 4; j++) wmma::fill_fragment(acc[i][j], 0.f);

#pragma unroll
    for (int s = 0; s < NSTG - 1; s++) {
        load_stage(tid, sAb, sBb, s, Ab, Bb, AST, BST, s);
        CP_COMMIT();
    }

    int su = 0;               // stage being consumed
    int sl = NSTG - 1;        // stage being loaded
    for (int kt = 0; kt < KT; kt++) {
        cp_wait<NSTG - 2>();
        __syncthreads();
        if (kt + NSTG - 1 < KT)
            load_stage(tid, sAb, sBb, sl, Ab, Bb, AST, BST, kt + NSTG - 1);
        CP_COMMIT();

#pragma unroll
        for (int ks = 0; ks < BK; ks += 16) {
            wmma::fragment<wmma::matrix_a, 16, 16, 16, __half, wmma::row_major> af[4];
#pragma unroll
            for (int i = 0; i < 4; i++)
                wmma::load_matrix_sync(af[i], &sA[su * A_ST + (wm * 64 + i * 16) * LDA + ks], LDA);
            wmma::fragment<wmma::matrix_b, 16, 16, 16, __half, wmma::row_major> bf[4];
#pragma unroll
            for (int j = 0; j < 4; j++)
                wmma::load_matrix_sync(bf[j], &sB[su * B_ST + ks * LDB + wn * 64 + j * 16], LDB);
#pragma unroll
            for (int i = 0; i < 4; i++)
#pragma unroll
                for (int j = 0; j < 4; j++)
                    wmma::mma_sync(acc[i][j], af[i], bf[j], acc[i][j]);
        }
        __syncthreads();
        su = (su == NSTG - 1) ? 0 : su + 1;
        sl = (sl == NSTG - 1) ? 0 : sl + 1;
    }

    // drain pipeline, then reuse stage smem; epilogue in two 32-row halves (8KB/warp)
    cp_wait<0>();
    __syncthreads();
    float* wtile = (float*)smem + warpId * 32 * 64;   // 8KB per warp, 32KB total

#pragma unroll
    for (int half = 0; half < 2; half++) {
#pragma unroll
        for (int i = 0; i < 2; i++)
#pragma unroll
            for (int j = 0; j < 4; j++)
                wmma::store_matrix_sync(&wtile[(i * 16) * 64 + j * 16],
                                        acc[half * 2 + i][j], 64, wmma::mem_row_major);
        __syncwarp();

        int gm0 = m0 + wm * 64 + half * 32;   // global row base for this half
        int gn0 = n0 + wn * 64;               // global col base

        if (G1) {
            const float* brow = bias + (size_t)e * FDIM + gn0;
#pragma unroll
            for (int it = 0; it < 8; it++) {
                int chunk = lane + 32 * it;       // 32 rows x 8 chunks
                int r = chunk >> 3, c8 = (chunk & 7) * 8;
                int m = gm0 + r;
                if (m < kept) {
                    float4 v0 = *(float4*)&wtile[r * 64 + c8];
                    float4 v1 = *(float4*)&wtile[r * 64 + c8 + 4];
                    float4 b0 = *(const float4*)&brow[c8];
                    float4 b1 = *(const float4*)&brow[c8 + 4];
                    float x0 = v0.x + b0.x, x1 = v0.y + b0.y, x2 = v0.z + b0.z, x3 = v0.w + b0.w;
                    float x4 = v1.x + b1.x, x5 = v1.y + b1.y, x6 = v1.z + b1.z, x7 = v1.w + b1.w;
                    const float IS2 = 0.70710678118654752f;
                    x0 = 0.5f * x0 * (1.f + erff(x0 * IS2));
                    x1 = 0.5f * x1 * (1.f + erff(x1 * IS2));
                    x2 = 0.5f * x2 * (1.f + erff(x2 * IS2));
                    x3 = 0.5f * x3 * (1.f + erff(x3 * IS2));
                    x4 = 0.5f * x4 * (1.f + erff(x4 * IS2));
                    x5 = 0.5f * x5 * (1.f + erff(x5 * IS2));
                    x6 = 0.5f * x6 * (1.f + erff(x6 * IS2));
                    x7 = 0.5f * x7 * (1.f + erff(x7 * IS2));
                    __half2 h0 = __floats2half2_rn(x0, x1);
                    __half2 h1 = __floats2half2_rn(x2, x3);
                    __half2 h2 = __floats2half2_rn(x4, x5);
                    __half2 h3 = __floats2half2_rn(x6, x7);
                    uint4 pkt;
                    pkt.x = *(uint32_t*)&h0; pkt.y = *(uint32_t*)&h1;
                    pkt.z = *(uint32_t*)&h2; pkt.w = *(uint32_t*)&h3;
                    *(uint4*)(g_h1 + ((size_t)e * CAP + m) * FDIM + gn0 + c8) = pkt;
                }
            }
        } else {
            const float* brow = bias + (size_t)e * HDIM + gn0;
#pragma unroll
            for (int it = 0; it < 8; it++) {
                int chunk = lane + 32 * it;
                int r = chunk >> 3, c8 = (chunk & 7) * 8;
                int m = gm0 + r;
                int tok = (m < kept) ? g_tok[e * CAP + m] : -1;
                if (tok >= 0) {
                    float gate = g_gate[e * CAP + m];
                    float4 v0 = *(float4*)&wtile[r * 64 + c8];
                    float4 v1 = *(float4*)&wtile[r * 64 + c8 + 4];
                    float4 b0 = *(const float4*)&brow[c8];
                    float4 b1 = *(const float4*)&brow[c8 + 4];
                    float* arow = g_accum + (size_t)tok * HDIM + gn0 + c8;
                    atomicAdd(&arow[0], (v0.x + b0.x) * gate);
                    atomicAdd(&arow[1], (v0.y + b0.y) * gate);
                    atomicAdd(&arow[2], (v0.z + b0.z) * gate);
                    atomicAdd(&arow[3], (v0.w + b0.w) * gate);
                    atomicAdd(&arow[4], (v1.x + b1.x) * gate);
                    atomicAdd(&arow[5], (v1.y + b1.y) * gate);
                    atomicAdd(&arow[6], (v1.z + b1.z) * gate);
                    atomicAdd(&arow[7], (v1.w + b1.w) * gate);
                }
            }
        }
        __syncwarp();
    }
}

// ---------------- LayerNorm over accum -> out ----------------
__global__ void ln_kernel(const float* __restrict__ gamma,
                          const float* __restrict__ beta,
                          float* __restrict__ out) {
    int row = blockIdx.x, tid = threadIdx.x;
    const float4* a = (const float4*)(g_accum + (size_t)row * HDIM);
    float4 v = a[tid];
    float s = v.x + v.y + v.z + v.w;
    float q = v.x * v.x + v.y * v.y + v.z * v.z + v.w * v.w;
#pragma unroll
    for (int o = 16; o; o >>= 1) {
        s += __shfl_xor_sync(0xFFFFFFFFu, s, o);
        q += __shfl_xor_sync(0xFFFFFFFFu, q, o);
    }
    __shared__ float ss[8], sq[8];
    if ((tid & 31) == 0) { ss[tid >> 5] = s; sq[tid >> 5] = q; }
    __syncthreads();
    if (tid < 32) {
        s = (tid < 8) ? ss[tid] : 0.f;
        q = (tid < 8) ? sq[tid] : 0.f;
#pragma unroll
        for (int o = 4; o; o >>= 1) {
            s += __shfl_xor_sync(0xFFFFFFFFu, s, o);
            q += __shfl_xor_sync(0xFFFFFFFFu, q, o);
        }
        if (tid == 0) { ss[0] = s; sq[0] = q; }
    }
    __syncthreads();
    float mu = ss[0] * (1.f / HDIM);
    float var = sq[0] * (1.f / HDIM) - mu * mu;
    float rs = rsqrtf(var + 1e-5f);
    float4 gv = ((const float4*)gamma)[tid];
    float4 bv = ((const float4*)beta)[tid];
    float4 o4;
    o4.x = (v.x - mu) * rs * gv.x + bv.x;
    o4.y = (v.y - mu) * rs * gv.y + bv.y;
    o4.z = (v.z - mu) * rs * gv.z + bv.z;
    o4.w = (v.w - mu) * rs * gv.w + bv.w;
    ((float4*)(out + (size_t)row * HDIM))[tid] = o4;
}

// ---------------- launch (single stream — no resource creation) ----------------
extern "C" void kernel_launch(void* const* d_in, const int* in_sizes, int n_in,
                              void* d_out, int out_size) {
    const float* hidden = (const float*)d_in[0];
    const float* Wr     = (const float*)d_in[1];
    const float* br     = (const float*)d_in[2];
    const float* W1     = (const float*)d_in[3];
    const float* b1     = (const float*)d_in[4];
    const float* W2     = (const float*)d_in[5];
    const float* b2     = (const float*)d_in[6];
    const float* gamma  = (const float*)d_in[7];
    const float* beta   = (const float*)d_in[8];
    float* out = (float*)d_out;

    cudaFuncSetAttribute(select_kernel, cudaFuncAttributeMaxDynamicSharedMemorySize,
                         BUCKET * sizeof(unsigned long long));
    cudaFuncSetAttribute(gemm_h<HDIM / BK, HDIM, FDIM, true>,
                         cudaFuncAttributeMaxDynamicSharedMemorySize, SMEM_NEED);
    cudaFuncSetAttribute(gemm_h<FDIM / BK, FDIM, HDIM, false>,
                         cudaFuncAttributeMaxDynamicSharedMemorySize, SMEM_NEED);

    __half* w1h; cudaGetSymbolAddress((void**)&w1h, g_w1h);
    __half* w2h; cudaGetSymbolAddress((void**)&w2h, g_w2h);

    size_t w4 = (size_t)NEXP * HDIM * FDIM / 4;
    size_t n4 = (size_t)NTOK * HDIM / 4;

    f2h_kernel<<<(unsigned)((w4 + 2047) / 2048), 512>>>(W1, w1h, w4);          // 1
    router_kernel<<<NTOK / 32, 256>>>(hidden, Wr, br);                          // 2
    select_kernel<<<NEXP, SEL_THREADS, BUCKET * sizeof(unsigned long long)>>>();// 3
    gather_kernel<<<NEXP * CAP, 256>>>(hidden);                                 // 4
    gemm_h<HDIM / BK, HDIM, FDIM, true>                                         // 5
        <<<dim3(FDIM / BN, CAP / BM, NEXP), NT_G, SMEM_NEED>>>(b1);
    f2h_kernel<<<(unsigned)((w4 + 2047) / 2048), 512>>>(W2, w2h, w4);           // 6
    init_kernel<<<(unsigned)((n4 + 511) / 512), 512>>>(hidden);                 // 7
    gemm_h<FDIM / BK, FDIM, HDIM, false>                                        // 8
        <<<dim3(HDIM / BN, CAP / BM, NEXP), NT_G, SMEM_NEED>>>(b2);
    ln_kernel<<<NTOK, 256>>>(gamma, beta, out);                                 // 9
}

// round 13
// speedup vs baseline: 1.3070x; 1.0557x over previous
#include <cuda_runtime.h>
#include <cuda_fp16.h>
#include <mma.h>
#include <cstdint>
#include <math.h>

using namespace nvcuda;

#define NTOK 8192
#define HDIM 1024
#define FDIM 4096
#define NEXP 8
#define CAP  1280
#define BUCKET 8192

#define BM 128
#define BN 128
#define BK 32
#define NT_G 128          // 4 warps, each owns a 64x64 tile
#define LDA 40            // BK + 8 halves pad
#define LDB 136           // BN + 8 halves pad
#define NSTG 3
#define A_ST (BM * LDA)   // halves per A stage
#define B_ST (BK * LDB)   // halves per B stage
#define SMEM_NEED (NSTG * (A_ST + B_ST) * 2)   // 56,832 B -> 3 CTAs/SM

#define KSPLIT2 2         // split-K for GEMM2 (wave quantization fix)

#define SEL_THREADS 1024

// ---------------- device scratch (no allocation allowed) ----------------
__device__ __half g_h1[(size_t)NEXP * CAP * FDIM];      // 84 MB fp16
__device__ __half g_xe[(size_t)NEXP * CAP * HDIM];      // 20 MB fp16 gathered A
__device__ __half g_w1h[(size_t)NEXP * HDIM * FDIM];    // 64 MB fp16 [E][K][N]
__device__ __half g_w2h[(size_t)NEXP * FDIM * HDIM];    // 64 MB fp16 [E][K][N]
__device__ float  g_accum[(size_t)NTOK * HDIM];         // 32 MB
__device__ unsigned long long g_bucket[NEXP * BUCKET];
__device__ int    g_cnt[NEXP];
__device__ int    g_tok[NEXP * CAP];
__device__ float  g_gate[NEXP * CAP];
__device__ int    g_kept[NEXP];

// ---------------- helpers ----------------
__device__ __forceinline__ uint32_t smem_u32(const void* p) {
    uint32_t a;
    asm("{ .reg .u64 t; cvta.to.shared.u64 t, %1; cvt.u32.u64 %0, t; }" : "=r"(a) : "l"(p));
    return a;
}
__device__ __forceinline__ void cp16(uint32_t s, const void* g) {
    asm volatile("cp.async.cg.shared.global [%0], [%1], 16;" :: "r"(s), "l"(g));
}
#define CP_COMMIT() asm volatile("cp.async.commit_group;" ::: "memory")
template <int N>
__device__ __forceinline__ void cp_wait() {
    asm volatile("cp.async.wait_group %0;" :: "n"(N) : "memory");
}

// ---------------- init: accum = hidden (residual), zero counts for next call ----------------
__global__ void init_kernel(const float* __restrict__ hidden) {
    size_t i = (size_t)blockIdx.x * blockDim.x + threadIdx.x;
    const float4* src = (const float4*)hidden;
    float4* dst = (float4*)g_accum;
    size_t n4 = (size_t)NTOK * HDIM / 4;
    if (i < n4) dst[i] = src[i];
    if (blockIdx.x == 0 && threadIdx.x < NEXP) g_cnt[threadIdx.x] = 0;
}

// ---------------- fp32 -> fp16 conversion (4x float4 per thread for MLP) ----------------
__global__ void f2h_kernel(const float* __restrict__ s, __half* __restrict__ d, size_t n4) {
    size_t base = (size_t)blockIdx.x * blockDim.x * 4 + threadIdx.x;
    float4 v[4];
    size_t idx[4];
#pragma unroll
    for (int i = 0; i < 4; i++) {
        idx[i] = base + (size_t)i * blockDim.x;
        if (idx[i] < n4) v[i] = ((const float4*)s)[idx[i]];
    }
#pragma unroll
    for (int i = 0; i < 4; i++) {
        if (idx[i] < n4) {
            __half2* dd = (__half2*)d;
            dd[2 * idx[i] + 0] = __floats2half2_rn(v[i].x, v[i].y);
            dd[2 * idx[i] + 1] = __floats2half2_rn(v[i].z, v[i].w);
        }
    }
}

// ---------------- router: 32 tokens/block, Wr transposed in smem ----------------
__global__ __launch_bounds__(256) void router_kernel(const float* __restrict__ x,
                                                     const float* __restrict__ Wr,
                                                     const float* __restrict__ br) {
    __shared__ float sWt[NEXP * HDIM];   // [e][k], 32KB
    int tid = threadIdx.x;
    for (int k = tid; k < HDIM; k += 256) {
        float4 a = ((const float4*)(Wr + k * NEXP))[0];
        float4 b = ((const float4*)(Wr + k * NEXP))[1];
        sWt[0 * HDIM + k] = a.x; sWt[1 * HDIM + k] = a.y;
        sWt[2 * HDIM + k] = a.z; sWt[3 * HDIM + k] = a.w;
        sWt[4 * HDIM + k] = b.x; sWt[5 * HDIM + k] = b.y;
        sWt[6 * HDIM + k] = b.z; sWt[7 * HDIM + k] = b.w;
    }
    __syncthreads();

    int warp = tid >> 5, lane = tid & 31;
#pragma unroll
    for (int t = 0; t < 4; t++) {
        int tok = blockIdx.x * 32 + warp * 4 + t;
        const float4* xr = (const float4*)(x + (size_t)tok * HDIM);
        float acc[NEXP];
#pragma unroll
        for (int e = 0; e < NEXP; e++) acc[e] = 0.f;
#pragma unroll
        for (int i = 0; i < 8; i++) {
            float4 v = xr[lane + 32 * i];
#pragma unroll
            for (int e = 0; e < NEXP; e++) {
                float4 w = ((const float4*)(sWt + e * HDIM))[lane + 32 * i];
                acc[e] += v.x * w.x + v.y * w.y + v.z * w.z + v.w * w.w;
            }
        }
#pragma unroll
        for (int o = 16; o; o >>= 1)
#pragma unroll
            for (int e = 0; e < NEXP; e++) acc[e] += __shfl_xor_sync(0xFFFFFFFFu, acc[e], o);
        if (lane == 0) {
#pragma unroll
            for (int e = 0; e < NEXP; e++) acc[e] += br[e];
            int i0 = 0;
#pragma unroll
            for (int e = 1; e < NEXP; e++) if (acc[e] > acc[i0]) i0 = e;
            int i1 = -1;
#pragma unroll
            for (int e = 0; e < NEXP; e++) {
                if (e == i0) continue;
                if (i1 < 0 || acc[e] > acc[i1]) i1 = e;
            }
            float v0 = acc[i0], v1 = acc[i1];
            float e1 = __expf(v1 - v0);
            float inv = 1.f / (1.f + e1);
            float w0 = inv, w1 = e1 * inv;
            unsigned f0 = (unsigned)(tok * 2 + 0);
            unsigned f1 = (unsigned)(tok * 2 + 1);
            int p0 = atomicAdd(&g_cnt[i0], 1);
            g_bucket[i0 * BUCKET + p0] =
                ((unsigned long long)__float_as_uint(w0) << 32) | (0xFFFFFFFFu - f0);
            int p1 = atomicAdd(&g_cnt[i1], 1);
            g_bucket[i1 * BUCKET + p1] =
                ((unsigned long long)__float_as_uint(w1) << 32) | (0xFFFFFFFFu - f1);
        }
    }
}

// ---------------- per-expert capacity selection: radix select (order-free) ----------------
__global__ void select_kernel() {
    extern __shared__ unsigned long long skeys[];   // up to BUCKET keys (64KB)
    __shared__ int hist[256];
    __shared__ unsigned long long s_thr;
    __shared__ int s_rem;
    __shared__ int pos;
    int e = blockIdx.x;
    int cnt = g_cnt[e];
    int tid = threadIdx.x;
    for (int i = tid; i < cnt; i += SEL_THREADS)
        skeys[i] = g_bucket[e * BUCKET + i];
    int kept = min(cnt, CAP);
    if (tid == 0) { g_kept[e] = kept; pos = 0; }
    __syncthreads();

    unsigned long long thr = 0ULL;
    if (cnt > CAP) {
        unsigned long long prefix = 0ULL;
        int remaining = kept;
        for (int level = 7; level >= 0; level--) {
            for (int i = tid; i < 256; i += SEL_THREADS) hist[i] = 0;
            __syncthreads();
            int sh = level * 8;
            unsigned long long pmask = (level == 7) ? 0ULL : (~0ULL << (sh + 8));
            for (int i = tid; i < cnt; i += SEL_THREADS) {
                unsigned long long k = skeys[i];
                if ((k & pmask) == prefix)
                    atomicAdd(&hist[(int)((k >> sh) & 0xFF)], 1);
            }
            __syncthreads();
            if (tid == 0) {
                int cum = 0, b = 255;
                for (; b > 0; b--) {
                    if (cum + hist[b] >= remaining) break;
                    cum += hist[b];
                }
                s_rem = remaining - cum;
                s_thr = prefix | ((unsigned long long)b << sh);
            }
            __syncthreads();
            prefix = s_thr;
            remaining = s_rem;
            __syncthreads();
        }
        thr = prefix;   // exactly kept keys satisfy key >= thr
    }

    for (int i = tid; i < cnt; i += SEL_THREADS) {
        unsigned long long k = skeys[i];
        if (k >= thr) {
            int p = atomicAdd(&pos, 1);
            unsigned flat = 0xFFFFFFFFu - (unsigned)(k & 0xFFFFFFFFu);
            g_tok[e * CAP + p] = (int)(flat >> 1);
            g_gate[e * CAP + p] = __uint_as_float((unsigned)(k >> 32));
        }
    }
    __syncthreads();
    for (int i = kept + tid; i < CAP; i += SEL_THREADS) {
        g_tok[e * CAP + i] = -1;
        g_gate[e * CAP + i] = 0.f;
    }
}

// ---------------- gather: pack x[tok] -> fp16 dense A; zero padding ----------------
__global__ void gather_kernel(const float* __restrict__ x) {
    int slot = blockIdx.x;
    int tok = g_tok[slot];
    __half2* dst = (__half2*)(g_xe + (size_t)slot * HDIM);
    int t = threadIdx.x;
    if (tok >= 0) {
        float4 v = ((const float4*)(x + (size_t)tok * HDIM))[t];
        dst[2 * t + 0] = __floats2half2_rn(v.x, v.y);
        dst[2 * t + 1] = __floats2half2_rn(v.z, v.w);
    } else {
        dst[2 * t + 0] = __half2half2(__float2half(0.f));
        dst[2 * t + 1] = __half2half2(__float2half(0.f));
    }
}

// ---------------- stage loader: A [BM x BK], B [BK x BN] fp16, 128 threads ----------------
__device__ __forceinline__ void load_stage(int tid, uint32_t sAb, uint32_t sBb, int s,
                                           const __half* Ab, const __half* Bb,
                                           int astr, int bstr, int kt) {
#pragma unroll
    for (int i = 0; i < 4; i++) {          // A: 128 rows x 4 chunks(16B) = 512
        int c = tid + NT_G * i;
        int r = c >> 2, ch = c & 3;
        cp16(sAb + ((uint32_t)(s * A_ST + r * LDA + ch * 8)) * 2,
             Ab + (size_t)r * astr + kt * BK + ch * 8);
    }
#pragma unroll
    for (int i = 0; i < 4; i++) {          // B: 32 rows x 16 chunks(16B) = 512
        int c = tid + NT_G * i;
        int r = c >> 4, ch = c & 15;
        cp16(sBb + ((uint32_t)(s * B_ST + r * LDB + ch * 8)) * 2,
             Bb + (size_t)(kt * BK + r) * bstr + ch * 8);
    }
}

// ---------------- fp16 wmma GEMM, 4 warps x (64x64), 3 CTAs/SM, single-sync loop ----------------
// G1:  h1 = gelu(x[tok] @ W1 + b1)               KSPLIT = 1
// !G1: accum[tok] += gate*(h1 @ W2) partial; split 0 also adds gate*b2
template <int KT, int AST, int BST, bool G1, int KSPLIT>
__global__ void __launch_bounds__(NT_G, 3) gemm_h(const float* __restrict__ bias) {
    int ez = blockIdx.z;
    int e  = ez / KSPLIT;
    int sp = ez % KSPLIT;
    int kept = g_kept[e];
    int m0 = blockIdx.y * BM;
    if (m0 >= kept) return;
    int n0 = blockIdx.x * BN;
    const int KTC = KT / KSPLIT;
    const int k0 = sp * KTC;

    extern __shared__ __half smem[];
    __half* sA = smem;
    __half* sB = smem + NSTG * A_ST;
    uint32_t sAb = smem_u32(sA), sBb = smem_u32(sB);

    int tid = threadIdx.x;
    int warpId = tid >> 5, lane = tid & 31;
    int wm = warpId & 1, wn = warpId >> 1;    // 2x2 warp grid, 64x64 each

    const __half* Ab;
    const __half* Bb;
    if (G1) {
        Ab = g_xe + (size_t)(e * CAP + m0) * AST;
        Bb = g_w1h + (size_t)e * HDIM * FDIM + n0;
    } else {
        Ab = g_h1 + (size_t)(e * CAP + m0) * AST;
        Bb = g_w2h + (size_t)e * FDIM * HDIM + n0;
    }

    wmma::fragment<wmma::accumulator, 16, 16, 16, float> acc[4][4];
#pragma unroll
    for (int i = 0; i < 4; i++)
#pragma unroll
        for (int j = 0; j < 4; j++) wmma::fill_fragment(acc[i][j], 0.f);

#pragma unroll
    for (int s = 0; s < NSTG - 1; s++) {
        load_stage(tid, sAb, sBb, s, Ab, Bb, AST, BST, k0 + s);
        CP_COMMIT();
    }

    int su = 0;               // stage being consumed
    int sl = NSTG - 1;        // stage being loaded
    for (int kt = 0; kt < KTC; kt++) {
        cp_wait<NSTG - 2>();
        __syncthreads();      // single barrier per K-tile: all warps now in iter kt

#pragma unroll
        for (int ks = 0; ks < BK; ks += 16) {
            wmma::fragment<wmma::matrix_a, 16, 16, 16, __half, wmma::row_major> af[4];
#pragma unroll
            for (int i = 0; i < 4; i++)
                wmma::load_matrix_sync(af[i], &sA[su * A_ST + (wm * 64 + i * 16) * LDA + ks], LDA);
            wmma::fragment<wmma::matrix_b, 16, 16, 16, __half, wmma::row_major> bf[4];
#pragma unroll
            for (int j = 0; j < 4; j++)
                wmma::load_matrix_sync(bf[j], &sB[su * B_ST + ks * LDB + wn * 64 + j * 16], LDB);
#pragma unroll
            for (int i = 0; i < 4; i++)
#pragma unroll
                for (int j = 0; j < 4; j++)
                    wmma::mma_sync(acc[i][j], af[i], bf[j], acc[i][j]);
        }

        // load next stage AFTER consuming: writes stage sl != su (and != su+1),
        // so no barrier needed before the next iteration's cp_wait+sync.
        if (kt + NSTG - 1 < KTC)
            load_stage(tid, sAb, sBb, sl, Ab, Bb, AST, BST, k0 + kt + NSTG - 1);
        CP_COMMIT();

        su = (su == NSTG - 1) ? 0 : su + 1;
        sl = (sl == NSTG - 1) ? 0 : sl + 1;
    }

    // drain pipeline, then reuse stage smem; epilogue in two 32-row halves (8KB/warp)
    cp_wait<0>();
    __syncthreads();
    float* wtile = (float*)smem + warpId * 32 * 64;   // 8KB per warp, 32KB total

#pragma unroll
    for (int half = 0; half < 2; half++) {
#pragma unroll
        for (int i = 0; i < 2; i++)
#pragma unroll
            for (int j = 0; j < 4; j++)
                wmma::store_matrix_sync(&wtile[(i * 16) * 64 + j * 16],
                                        acc[half * 2 + i][j], 64, wmma::mem_row_major);
        __syncwarp();

        int gm0 = m0 + wm * 64 + half * 32;   // global row base for this half
        int gn0 = n0 + wn * 64;               // global col base

        if (G1) {
            const float* brow = bias + (size_t)e * FDIM + gn0;
#pragma unroll
            for (int it = 0; it < 8; it++) {
                int chunk = lane + 32 * it;       // 32 rows x 8 chunks
                int r = chunk >> 3, c8 = (chunk & 7) * 8;
                int m = gm0 + r;
                if (m < kept) {
                    float4 v0 = *(float4*)&wtile[r * 64 + c8];
                    float4 v1 = *(float4*)&wtile[r * 64 + c8 + 4];
                    float4 b0 = *(const float4*)&brow[c8];
                    float4 b1 = *(const float4*)&brow[c8 + 4];
                    float x0 = v0.x + b0.x, x1 = v0.y + b0.y, x2 = v0.z + b0.z, x3 = v0.w + b0.w;
                    float x4 = v1.x + b1.x, x5 = v1.y + b1.y, x6 = v1.z + b1.z, x7 = v1.w + b1.w;
                    const float IS2 = 0.70710678118654752f;
                    x0 = 0.5f * x0 * (1.f + erff(x0 * IS2));
                    x1 = 0.5f * x1 * (1.f + erff(x1 * IS2));
                    x2 = 0.5f * x2 * (1.f + erff(x2 * IS2));
                    x3 = 0.5f * x3 * (1.f + erff(x3 * IS2));
                    x4 = 0.5f * x4 * (1.f + erff(x4 * IS2));
                    x5 = 0.5f * x5 * (1.f + erff(x5 * IS2));
                    x6 = 0.5f * x6 * (1.f + erff(x6 * IS2));
                    x7 = 0.5f * x7 * (1.f + erff(x7 * IS2));
                    __half2 h0 = __floats2half2_rn(x0, x1);
                    __half2 h1 = __floats2half2_rn(x2, x3);
                    __half2 h2 = __floats2half2_rn(x4, x5);
                    __half2 h3 = __floats2half2_rn(x6, x7);
                    uint4 pkt;
                    pkt.x = *(uint32_t*)&h0; pkt.y = *(uint32_t*)&h1;
                    pkt.z = *(uint32_t*)&h2; pkt.w = *(uint32_t*)&h3;
                    *(uint4*)(g_h1 + ((size_t)e * CAP + m) * FDIM + gn0 + c8) = pkt;
                }
            }
        } else {
            const float* brow = bias + (size_t)e * HDIM + gn0;
#pragma unroll
            for (int it = 0; it < 8; it++) {
                int chunk = lane + 32 * it;
                int r = chunk >> 3, c8 = (chunk & 7) * 8;
                int m = gm0 + r;
                int tok = (m < kept) ? g_tok[e * CAP + m] : -1;
                if (tok >= 0) {
                    float gate = g_gate[e * CAP + m];
                    float4 v0 = *(float4*)&wtile[r * 64 + c8];
                    float4 v1 = *(float4*)&wtile[r * 64 + c8 + 4];
                    float4 b0, b1;
                    if (sp == 0) {
                        b0 = *(const float4*)&brow[c8];
                        b1 = *(const float4*)&brow[c8 + 4];
                    } else {
                        b0 = make_float4(0.f, 0.f, 0.f, 0.f);
                        b1 = make_float4(0.f, 0.f, 0.f, 0.f);
                    }
                    float* arow = g_accum + (size_t)tok * HDIM + gn0 + c8;
                    atomicAdd(&arow[0], (v0.x + b0.x) * gate);
                    atomicAdd(&arow[1], (v0.y + b0.y) * gate);
                    atomicAdd(&arow[2], (v0.z + b0.z) * gate);
                    atomicAdd(&arow[3], (v0.w + b0.w) * gate);
                    atomicAdd(&arow[4], (v1.x + b1.x) * gate);
                    atomicAdd(&arow[5], (v1.y + b1.y) * gate);
                    atomicAdd(&arow[6], (v1.z + b1.z) * gate);
                    atomicAdd(&arow[7], (v1.w + b1.w) * gate);
                }
            }
        }
        __syncwarp();
    }
}

// ---------------- LayerNorm over accum -> out ----------------
__global__ void ln_kernel(const float* __restrict__ gamma,
                          const float* __restrict__ beta,
                          float* __restrict__ out) {
    int row = blockIdx.x, tid = threadIdx.x;
    const float4* a = (const float4*)(g_accum + (size_t)row * HDIM);
    float4 v = a[tid];
    float s = v.x + v.y + v.z + v.w;
    float q = v.x * v.x + v.y * v.y + v.z * v.z + v.w * v.w;
#pragma unroll
    for (int o = 16; o; o >>= 1) {
        s += __shfl_xor_sync(0xFFFFFFFFu, s, o);
        q += __shfl_xor_sync(0xFFFFFFFFu, q, o);
    }
    __shared__ float ss[8], sq[8];
    if ((tid & 31) == 0) { ss[tid >> 5] = s; sq[tid >> 5] = q; }
    __syncthreads();
    if (tid < 32) {
        s = (tid < 8) ? ss[tid] : 0.f;
        q = (tid < 8) ? sq[tid] : 0.f;
#pragma unroll
        for (int o = 4; o; o >>= 1) {
            s += __shfl_xor_sync(0xFFFFFFFFu, s, o);
            q += __shfl_xor_sync(0xFFFFFFFFu, q, o);
        }
        if (tid == 0) { ss[0] = s; sq[0] = q; }
    }
    __syncthreads();
    float mu = ss[0] * (1.f / HDIM);
    float var = sq[0] * (1.f / HDIM) - mu * mu;
    float rs = rsqrtf(var + 1e-5f);
    float4 gv = ((const float4*)gamma)[tid];
    float4 bv = ((const float4*)beta)[tid];
    float4 o4;
    o4.x = (v.x - mu) * rs * gv.x + bv.x;
    o4.y = (v.y - mu) * rs * gv.y + bv.y;
    o4.z = (v.z - mu) * rs * gv.z + bv.z;
    o4.w = (v.w - mu) * rs * gv.w + bv.w;
    ((float4*)(out + (size_t)row * HDIM))[tid] = o4;
}

// ---------------- launch (single stream — no resource creation) ----------------
extern "C" void kernel_launch(void* const* d_in, const int* in_sizes, int n_in,
                              void* d_out, int out_size) {
    const float* hidden = (const float*)d_in[0];
    const float* Wr     = (const float*)d_in[1];
    const float* br     = (const float*)d_in[2];
    const float* W1     = (const float*)d_in[3];
    const float* b1     = (const float*)d_in[4];
    const float* W2     = (const float*)d_in[5];
    const float* b2     = (const float*)d_in[6];
    const float* gamma  = (const float*)d_in[7];
    const float* beta   = (const float*)d_in[8];
    float* out = (float*)d_out;

    cudaFuncSetAttribute(select_kernel, cudaFuncAttributeMaxDynamicSharedMemorySize,
                         BUCKET * sizeof(unsigned long long));
    cudaFuncSetAttribute(gemm_h<HDIM / BK, HDIM, FDIM, true, 1>,
                         cudaFuncAttributeMaxDynamicSharedMemorySize, SMEM_NEED);
    cudaFuncSetAttribute(gemm_h<FDIM / BK, FDIM, HDIM, false, KSPLIT2>,
                         cudaFuncAttributeMaxDynamicSharedMemorySize, SMEM_NEED);

    __half* w1h; cudaGetSymbolAddress((void**)&w1h, g_w1h);
    __half* w2h; cudaGetSymbolAddress((void**)&w2h, g_w2h);

    size_t w4 = (size_t)NEXP * HDIM * FDIM / 4;
    size_t n4 = (size_t)NTOK * HDIM / 4;

    f2h_kernel<<<(unsigned)((w4 + 2047) / 2048), 512>>>(W1, w1h, w4);          // 1
    router_kernel<<<NTOK / 32, 256>>>(hidden, Wr, br);                          // 2
    select_kernel<<<NEXP, SEL_THREADS, BUCKET * sizeof(unsigned long long)>>>();// 3
    gather_kernel<<<NEXP * CAP, 256>>>(hidden);                                 // 4
    gemm_h<HDIM / BK, HDIM, FDIM, true, 1>                                      // 5
        <<<dim3(FDIM / BN, CAP / BM, NEXP), NT_G, SMEM_NEED>>>(b1);
    f2h_kernel<<<(unsigned)((w4 + 2047) / 2048), 512>>>(W2, w2h, w4);           // 6
    init_kernel<<<(unsigned)((n4 + 511) / 512), 512>>>(hidden);                 // 7
    gemm_h<FDIM / BK, FDIM, HDIM, false, KSPLIT2>                               // 8
        <<<dim3(HDIM / BN, CAP / BM, NEXP * KSPLIT2), NT_G, SMEM_NEED>>>(b2);
    ln_kernel<<<NTOK, 256>>>(gamma, beta, out);                                 // 9
}